// round 1
// baseline (speedup 1.0000x reference)
#include <cuda_runtime.h>

// DeepFeatureLoss: out[b] = sum_i w[b,i] * sum_j (p_ij - q_ij)^2
//   p = softmax_j(-||x_i/s - x_j/s||^2)   (max over j is 0, at j==i)
//   q = softmax_j(-||f1_i - f2_j||^2)     (online max needed)
// Decomposition: sum_j (p-q)^2 = B/Zp^2 - 2A/(Zp*Zq) + C/Zq^2 with
//   Zp=sum e_p, B=sum e_p^2, Zq=sum e_q, C=sum e_q^2, A=sum e_p*e_q
// accumulated online per (row, j-chunk), merged in a reduce kernel.

#define SIGMA_INV 20.0f        // 1/0.05
#define S_CHUNKS  16           // j-chunks per row
#define R_ROWS    256          // rows per block (== threads per block)
#define TJ        128          // j-tile staged in shared

#define MAX_ROWS  16384

// per-j record: 10 float4 = [0..7]: 2*f2 (8x float4), [8]: (2u0,2u1,2u2, -|u|^2), [9]: (-|f2|^2, pad..)
static __device__ __align__(16) float4 g_rec[MAX_ROWS * 10];
// per (row, chunk) partial: 2 float4 = (mq, Zq, A, C), (Zp, B, 0, 0)
static __device__ __align__(16) float4 g_part[MAX_ROWS * S_CHUNKS * 2];

__global__ void prep_kernel(const float* __restrict__ points,
                            const float* __restrict__ fea2,
                            int BN)
{
    int g = blockIdx.x * blockDim.x + threadIdx.x;
    if (g >= BN) return;

    float4 r[10];
    const float4* f2 = (const float4*)(fea2 + (size_t)g * 32);
    float cf = 0.f;
#pragma unroll
    for (int q = 0; q < 8; q++) {
        float4 v = f2[q];
        cf = fmaf(v.x, v.x, cf); cf = fmaf(v.y, v.y, cf);
        cf = fmaf(v.z, v.z, cf); cf = fmaf(v.w, v.w, cf);
        r[q] = make_float4(2.f * v.x, 2.f * v.y, 2.f * v.z, 2.f * v.w);
    }
    float u0 = points[(size_t)g * 3 + 0] * SIGMA_INV;
    float u1 = points[(size_t)g * 3 + 1] * SIGMA_INV;
    float u2 = points[(size_t)g * 3 + 2] * SIGMA_INV;
    float cx = -(u0 * u0 + u1 * u1 + u2 * u2);
    r[8] = make_float4(2.f * u0, 2.f * u1, 2.f * u2, cx);
    r[9] = make_float4(-cf, 0.f, 0.f, 0.f);

#pragma unroll
    for (int q = 0; q < 10; q++) g_rec[(size_t)g * 10 + q] = r[q];
}

__global__ __launch_bounds__(R_ROWS) void main_kernel(
    const float* __restrict__ fea1,
    const float* __restrict__ points,
    int N)
{
    __shared__ __align__(16) float4 srec[TJ * 10];

    const int rowblk = blockIdx.x / S_CHUNKS;
    const int chunk  = blockIdx.x % S_CHUNKS;
    const int g = rowblk * R_ROWS + threadIdx.x;   // global row (all rows in block share batch)
    const int b = g / N;
    const int JC = N / S_CHUNKS;
    const int j0 = b * N + chunk * JC;

    // per-row constants in registers
    float4 f1[8];
    const float4* f1p = (const float4*)(fea1 + (size_t)g * 32);
#pragma unroll
    for (int q = 0; q < 8; q++) f1[q] = f1p[q];
    float u0 = points[(size_t)g * 3 + 0] * SIGMA_INV;
    float u1 = points[(size_t)g * 3 + 1] * SIGMA_INV;
    float u2 = points[(size_t)g * 3 + 2] * SIGMA_INV;
    float ci = -(u0 * u0 + u1 * u1 + u2 * u2);

    float mq = -3.0e38f, Zq = 0.f, A = 0.f, C = 0.f, Zp = 0.f, Bb = 0.f;

    for (int t0 = 0; t0 < JC; t0 += TJ) {
        __syncthreads();
        const float4* src = &g_rec[(size_t)(j0 + t0) * 10];
        for (int t = threadIdx.x; t < TJ * 10; t += R_ROWS) srec[t] = src[t];
        __syncthreads();

        for (int jj = 0; jj < TJ; jj++) {
            const float4* rv = &srec[jj * 10];
            float4 v8 = rv[8];
            float4 v9 = rv[9];

            // feature score: sq = 2*f1.f2 - |f2|^2  (4 accumulator chains)
            float a0 = v9.x, a1 = 0.f, a2 = 0.f, a3 = 0.f;
#pragma unroll
            for (int q = 0; q < 8; q += 4) {
                float4 w0 = rv[q + 0], w1 = rv[q + 1], w2 = rv[q + 2], w3 = rv[q + 3];
                a0 = fmaf(f1[q + 0].x, w0.x, a0); a0 = fmaf(f1[q + 0].y, w0.y, a0);
                a0 = fmaf(f1[q + 0].z, w0.z, a0); a0 = fmaf(f1[q + 0].w, w0.w, a0);
                a1 = fmaf(f1[q + 1].x, w1.x, a1); a1 = fmaf(f1[q + 1].y, w1.y, a1);
                a1 = fmaf(f1[q + 1].z, w1.z, a1); a1 = fmaf(f1[q + 1].w, w1.w, a1);
                a2 = fmaf(f1[q + 2].x, w2.x, a2); a2 = fmaf(f1[q + 2].y, w2.y, a2);
                a2 = fmaf(f1[q + 2].z, w2.z, a2); a2 = fmaf(f1[q + 2].w, w2.w, a2);
                a3 = fmaf(f1[q + 3].x, w3.x, a3); a3 = fmaf(f1[q + 3].y, w3.y, a3);
                a3 = fmaf(f1[q + 3].z, w3.z, a3); a3 = fmaf(f1[q + 3].w, w3.w, a3);
            }
            float sq = (a0 + a1) + (a2 + a3);

            // spatial score: sp = 2*u_i.u_j - |u_i|^2 - |u_j|^2  (<= 0, max at j==i)
            float sp = ci + v8.w;
            sp = fmaf(u0, v8.x, sp);
            sp = fmaf(u1, v8.y, sp);
            sp = fmaf(u2, v8.z, sp);
            float ep = __expf(sp);

            // online-max stats for q
            float nm = fmaxf(mq, sq);
            float r  = __expf(mq - nm);    // 1 if max unchanged, 0/scale otherwise
            float eq = __expf(sq - nm);
            Zq = fmaf(Zq, r, eq);
            A  = fmaf(A,  r, ep * eq);
            C  = fmaf(C,  r * r, eq * eq);
            mq = nm;
            Zp += ep;
            Bb = fmaf(ep, ep, Bb);
        }
    }

    size_t p = ((size_t)g * S_CHUNKS + chunk) * 2;
    g_part[p + 0] = make_float4(mq, Zq, A, C);
    g_part[p + 1] = make_float4(Zp, Bb, 0.f, 0.f);
}

__global__ void reduce_kernel(const float* __restrict__ weights,
                              float* __restrict__ out, int N)
{
    __shared__ float sred[256];
    int b = blockIdx.x;
    float sum = 0.f;

    for (int i = threadIdx.x; i < N; i += 256) {
        int g = b * N + i;
        float m = -3.0e38f;
#pragma unroll
        for (int k = 0; k < S_CHUNKS; k++)
            m = fmaxf(m, g_part[((size_t)g * S_CHUNKS + k) * 2].x);
        float Zq = 0.f, A = 0.f, C = 0.f, Zp = 0.f, Bb = 0.f;
#pragma unroll
        for (int k = 0; k < S_CHUNKS; k++) {
            float4 p0 = g_part[((size_t)g * S_CHUNKS + k) * 2 + 0];
            float4 p1 = g_part[((size_t)g * S_CHUNKS + k) * 2 + 1];
            float e = __expf(p0.x - m);
            Zq = fmaf(p0.y, e, Zq);
            A  = fmaf(p0.z, e, A);
            C  = fmaf(p0.w, e * e, C);
            Zp += p1.x;
            Bb += p1.y;
        }
        float izp = 1.f / Zp, izq = 1.f / Zq;
        float loss = Bb * izp * izp - 2.f * A * izp * izq + C * izq * izq;
        sum = fmaf(weights[g], loss, sum);
    }

    sred[threadIdx.x] = sum;
    __syncthreads();
#pragma unroll
    for (int s = 128; s > 0; s >>= 1) {
        if (threadIdx.x < s) sred[threadIdx.x] += sred[threadIdx.x + s];
        __syncthreads();
    }
    if (threadIdx.x == 0) out[b] = sred[0];
}

extern "C" void kernel_launch(void* const* d_in, const int* in_sizes, int n_in,
                              void* d_out, int out_size)
{
    const float* points  = (const float*)d_in[0];  // [B,N,3]
    const float* fea1    = (const float*)d_in[1];  // [B,N,32]
    const float* fea2    = (const float*)d_in[2];  // [B,N,32]
    const float* weights = (const float*)d_in[3];  // [B,N]

    int BN = in_sizes[3];          // B*N
    int B  = out_size;             // output is [B]
    int N  = BN / B;

    prep_kernel<<<(BN + 255) / 256, 256>>>(points, fea2, BN);

    int rowblks = BN / R_ROWS;
    main_kernel<<<rowblks * S_CHUNKS, R_ROWS>>>(fea1, points, N);

    reduce_kernel<<<B, 256>>>(weights, (float*)d_out, N);
}

// round 2
// speedup vs baseline: 1.1771x; 1.1771x over previous
#include <cuda_runtime.h>

// DeepFeatureLoss: out[b] = sum_i w[b,i] * sum_j (p_ij - q_ij)^2
//   p = softmax_j over -||x_i/s - x_j/s||^2      (scores <= 0, max at j==i)
//   q = softmax_j over -||f1_i - f2_j||^2        (scores <= 0 too -> NO online max!)
// sum_j (p-q)^2 = B/Zp^2 - 2A/(Zp Zq) + C/Zq^2,
//   Zp=sum ep, B=sum ep^2, Zq=sum eq, A=sum ep*eq, C=sum eq^2.
// eq carries a fixed 2^KSH shift + per-row constant; both cancel in the ratios.
// Records pre-scaled by 2*log2e so exps are bare ex2.approx.

#define SIGMA_INV 20.0f
#define LOG2E     1.4426950408889634f
#define KSH       44.0f
#define S_CHUNKS  16
#define R_ROWS    128
#define TJ        128
#define MAX_ROWS  16384

// per-j record, 10 float4:
// [0..7]: 2*log2e*f2 (32 floats)
// [8]:    (2L*u0, 2L*u1, 2L*u2, -L*|u|^2)
// [9]:    (-L*|f2|^2, 0, 0, 0)
static __device__ __align__(16) float4 g_rec[MAX_ROWS * 10];
// per (row, chunk) partial: (Zq, A, C, Zp), (Bb, 0, 0, 0)
static __device__ __align__(16) float4 g_part[MAX_ROWS * S_CHUNKS * 2];

__device__ __forceinline__ unsigned long long f2mul(unsigned long long a, unsigned long long b) {
    unsigned long long d;
    asm("mul.rn.f32x2 %0, %1, %2;" : "=l"(d) : "l"(a), "l"(b));
    return d;
}
__device__ __forceinline__ unsigned long long f2fma(unsigned long long a, unsigned long long b, unsigned long long c) {
    unsigned long long d;
    asm("fma.rn.f32x2 %0, %1, %2, %3;" : "=l"(d) : "l"(a), "l"(b), "l"(c));
    return d;
}
__device__ __forceinline__ unsigned long long f2add(unsigned long long a, unsigned long long b) {
    unsigned long long d;
    asm("add.rn.f32x2 %0, %1, %2;" : "=l"(d) : "l"(a), "l"(b));
    return d;
}
__device__ __forceinline__ float ex2f(float x) {
    float y;
    asm("ex2.approx.f32 %0, %1;" : "=f"(y) : "f"(x));
    return y;
}
__device__ __forceinline__ void unpack2(unsigned long long v, float& lo, float& hi) {
    asm("mov.b64 {%0, %1}, %2;" : "=f"(lo), "=f"(hi) : "l"(v));
}
__device__ __forceinline__ unsigned long long pack2(float lo, float hi) {
    unsigned long long v;
    asm("mov.b64 %0, {%1, %2};" : "=l"(v) : "f"(lo), "f"(hi));
    return v;
}

__global__ void prep_kernel(const float* __restrict__ points,
                            const float* __restrict__ fea2,
                            int BN)
{
    int g = blockIdx.x * blockDim.x + threadIdx.x;
    if (g >= BN) return;

    float4 r[10];
    const float4* f2 = (const float4*)(fea2 + (size_t)g * 32);
    float cf = 0.f;
#pragma unroll
    for (int q = 0; q < 8; q++) {
        float4 v = f2[q];
        cf = fmaf(v.x, v.x, cf); cf = fmaf(v.y, v.y, cf);
        cf = fmaf(v.z, v.z, cf); cf = fmaf(v.w, v.w, cf);
        float s = 2.f * LOG2E;
        r[q] = make_float4(s * v.x, s * v.y, s * v.z, s * v.w);
    }
    float u0 = points[(size_t)g * 3 + 0] * SIGMA_INV;
    float u1 = points[(size_t)g * 3 + 1] * SIGMA_INV;
    float u2 = points[(size_t)g * 3 + 2] * SIGMA_INV;
    float cu = -(u0 * u0 + u1 * u1 + u2 * u2) * LOG2E;
    float s = 2.f * LOG2E;
    r[8] = make_float4(s * u0, s * u1, s * u2, cu);
    r[9] = make_float4(-cf * LOG2E, 0.f, 0.f, 0.f);

#pragma unroll
    for (int q = 0; q < 10; q++) g_rec[(size_t)g * 10 + q] = r[q];
}

__global__ __launch_bounds__(R_ROWS) void main_kernel(
    const float* __restrict__ fea1,
    const float* __restrict__ points,
    int N)
{
    __shared__ __align__(16) float4 srec[TJ * 10];

    const int rowblk = blockIdx.x / S_CHUNKS;
    const int chunk  = blockIdx.x % S_CHUNKS;
    const int g = rowblk * R_ROWS + threadIdx.x;
    const int b = g / N;
    const int JC = N / S_CHUNKS;
    const int j0 = b * N + chunk * JC;

    // row constants in registers
    float4 f1q[8];
    const float4* f1p = (const float4*)(fea1 + (size_t)g * 32);
    float nf = 0.f;
#pragma unroll
    for (int q = 0; q < 8; q++) {
        f1q[q] = f1p[q];
        nf = fmaf(f1q[q].x, f1q[q].x, nf); nf = fmaf(f1q[q].y, f1q[q].y, nf);
        nf = fmaf(f1q[q].z, f1q[q].z, nf); nf = fmaf(f1q[q].w, f1q[q].w, nf);
    }
    unsigned long long rp[16];
#pragma unroll
    for (int q = 0; q < 8; q++) {
        rp[2 * q + 0] = pack2(f1q[q].x, f1q[q].y);
        rp[2 * q + 1] = pack2(f1q[q].z, f1q[q].w);
    }
    const float cq = KSH - nf * LOG2E;  // log2-domain row shift for feature exp

    float u0 = points[(size_t)g * 3 + 0] * SIGMA_INV;
    float u1 = points[(size_t)g * 3 + 1] * SIGMA_INV;
    float u2 = points[(size_t)g * 3 + 2] * SIGMA_INV;
    const float cp = -(u0 * u0 + u1 * u1 + u2 * u2) * LOG2E;

    float Zq = 0.f, A = 0.f, C = 0.f, Zp = 0.f, Bb = 0.f;

    for (int t0 = 0; t0 < JC; t0 += TJ) {
        __syncthreads();
        const float4* src = &g_rec[(size_t)(j0 + t0) * 10];
        for (int t = threadIdx.x; t < TJ * 10; t += R_ROWS) srec[t] = src[t];
        __syncthreads();

        int cnt = (JC - t0 < TJ) ? (JC - t0) : TJ;
#pragma unroll 2
        for (int jj = 0; jj < cnt; jj++) {
            const unsigned long long* rv = (const unsigned long long*)&srec[jj * 10];
            // 32-dim dot in packed f32x2: 16 FFMA2 across 4 accumulator chains
            unsigned long long a0 = f2mul(rp[0], rv[0]);
            unsigned long long a1 = f2mul(rp[1], rv[1]);
            unsigned long long a2 = f2mul(rp[2], rv[2]);
            unsigned long long a3 = f2mul(rp[3], rv[3]);
            a0 = f2fma(rp[4],  rv[4],  a0);
            a1 = f2fma(rp[5],  rv[5],  a1);
            a2 = f2fma(rp[6],  rv[6],  a2);
            a3 = f2fma(rp[7],  rv[7],  a3);
            a0 = f2fma(rp[8],  rv[8],  a0);
            a1 = f2fma(rp[9],  rv[9],  a1);
            a2 = f2fma(rp[10], rv[10], a2);
            a3 = f2fma(rp[11], rv[11], a3);
            a0 = f2fma(rp[12], rv[12], a0);
            a1 = f2fma(rp[13], rv[13], a1);
            a2 = f2fma(rp[14], rv[14], a2);
            a3 = f2fma(rp[15], rv[15], a3);
            unsigned long long ss = f2add(f2add(a0, a1), f2add(a2, a3));
            float lo, hi;
            unpack2(ss, lo, hi);

            float4 v8 = srec[jj * 10 + 8];
            float v9x = srec[jj * 10 + 9].x;

            float sq2 = (lo + hi) + (v9x + cq);                        // log2(eq)
            float sp2 = fmaf(u0, v8.x,
                        fmaf(u1, v8.y,
                        fmaf(u2, v8.z, cp + v8.w)));                   // log2(ep)
            float eq = ex2f(sq2);
            float ep = ex2f(sp2);

            Zq += eq;
            Zp += ep;
            A  = fmaf(ep, eq, A);
            C  = fmaf(eq, eq, C);
            Bb = fmaf(ep, ep, Bb);
        }
    }

    size_t p = ((size_t)g * S_CHUNKS + chunk) * 2;
    g_part[p + 0] = make_float4(Zq, A, C, Zp);
    g_part[p + 1] = make_float4(Bb, 0.f, 0.f, 0.f);
}

__global__ void reduce_kernel(const float* __restrict__ weights,
                              float* __restrict__ out, int N)
{
    __shared__ float sred[256];
    int b = blockIdx.x;
    float sum = 0.f;

    for (int i = threadIdx.x; i < N; i += 256) {
        int g = b * N + i;
        float Zq = 0.f, A = 0.f, C = 0.f, Zp = 0.f, Bb = 0.f;
#pragma unroll
        for (int k = 0; k < S_CHUNKS; k++) {
            float4 p0 = g_part[((size_t)g * S_CHUNKS + k) * 2 + 0];
            float4 p1 = g_part[((size_t)g * S_CHUNKS + k) * 2 + 1];
            Zq += p0.x; A += p0.y; C += p0.z; Zp += p0.w; Bb += p1.x;
        }
        float izp = 1.f / Zp, izq = 1.f / Zq;
        float loss = Bb * izp * izp - 2.f * A * izp * izq + C * izq * izq;
        sum = fmaf(weights[g], loss, sum);
    }

    sred[threadIdx.x] = sum;
    __syncthreads();
#pragma unroll
    for (int s = 128; s > 0; s >>= 1) {
        if (threadIdx.x < s) sred[threadIdx.x] += sred[threadIdx.x + s];
        __syncthreads();
    }
    if (threadIdx.x == 0) out[b] = sred[0];
}

extern "C" void kernel_launch(void* const* d_in, const int* in_sizes, int n_in,
                              void* d_out, int out_size)
{
    const float* points  = (const float*)d_in[0];  // [B,N,3]
    const float* fea1    = (const float*)d_in[1];  // [B,N,32]
    const float* fea2    = (const float*)d_in[2];  // [B,N,32]
    const float* weights = (const float*)d_in[3];  // [B,N]

    int BN = in_sizes[3];
    int B  = out_size;
    int N  = BN / B;

    prep_kernel<<<(BN + 255) / 256, 256>>>(points, fea2, BN);

    int rowblks = (BN + R_ROWS - 1) / R_ROWS;
    main_kernel<<<rowblks * S_CHUNKS, R_ROWS>>>(fea1, points, N);

    reduce_kernel<<<B, 256>>>(weights, (float*)d_out, N);
}